// round 15
// baseline (speedup 1.0000x reference)
#include <cuda_runtime.h>
#include <cuda_bf16.h>
#include <cuda_fp16.h>
#include <cstdint>
#include <math.h>

#define B_   2
#define T_   2048
#define HID_ 2048
#define NK_  16
#define DK_  128
#define NV_  32
#define DV_  128
#define KC_  4
#define P_   2
#define QD_  (NK_*DK_)        // 2048
#define VD_  (NV_*DV_)        // 4096
#define QKV_ (2*QD_+VD_)      // 8192
#define SV_  (P_*DV_)         // 256
#define BT_  (B_*T_)          // 4096
#define NZB_ (VD_ + 256)      // 4352 combined (z | ba-pad)

typedef unsigned long long u64;

// ---------------- scratch (device globals; no allocation allowed) ----------
__device__ __align__(16) float g_qkv [(size_t)BT_ * QKV_];   // raw qkv projection
__device__ __align__(16) float g_qkvc[(size_t)BT_ * QKV_];   // post-conv
__device__ __align__(16) float g_zba [(size_t)BT_ * NZB_];   // z | beta/dt pre-activation
__device__ __align__(16) float g_att [(size_t)BT_ * VD_];    // scan output
__device__ float g_beta [BT_ * NV_];
__device__ float g_decay[BT_ * NV_];

// fp16x2 split operands (K' = 2K):  A-side [hi|lo], B-side [hi|hi]
__device__ __align__(16) __half g_x2   [(size_t)BT_  * 2 * HID_];
__device__ __align__(16) __half g_wq2  [(size_t)QKV_ * 2 * HID_];
__device__ __align__(16) __half g_wzba2[(size_t)NZB_ * 2 * HID_];  // W_z | W_ba(pad)
__device__ __align__(16) __half g_wo2  [(size_t)HID_ * 2 * VD_];
__device__ __align__(16) __half g_att2 [(size_t)BT_  * 2 * VD_];

// ================= PTX helpers ==============================================
__device__ __forceinline__ uint32_t smem_to_u32(const void* p) {
    uint32_t a;
    asm("{ .reg .u64 t; cvta.to.shared.u64 t, %1; cvt.u32.u64 %0, t; }" : "=r"(a) : "l"(p));
    return a;
}
__device__ __forceinline__ void cp_async16(uint32_t dst, const void* src) {
    asm volatile("cp.async.cg.shared.global [%0], [%1], 16;" :: "r"(dst), "l"(src) : "memory");
}
#define CP_COMMIT() asm volatile("cp.async.commit_group;" ::: "memory")
#define CP_WAIT1()  asm volatile("cp.async.wait_group 1;"  ::: "memory")

__device__ __forceinline__ void ldm_x4(uint32_t* r, uint32_t a) {
    asm volatile("ldmatrix.sync.aligned.m8n8.x4.shared.b16 {%0,%1,%2,%3}, [%4];"
        : "=r"(r[0]), "=r"(r[1]), "=r"(r[2]), "=r"(r[3]) : "r"(a));
}
__device__ __forceinline__ void mma16816(float* d, const uint32_t* a, uint32_t b0, uint32_t b1) {
    asm volatile("mma.sync.aligned.m16n8k16.row.col.f32.f16.f16.f32 "
        "{%0,%1,%2,%3}, {%4,%5,%6,%7}, {%8,%9}, {%0,%1,%2,%3};"
        : "+f"(d[0]), "+f"(d[1]), "+f"(d[2]), "+f"(d[3])
        : "r"(a[0]), "r"(a[1]), "r"(a[2]), "r"(a[3]), "r"(b0), "r"(b1));
}

// packed fp32x2 (Blackwell)
__device__ __forceinline__ u64 pack2(float lo, float hi) {
    u64 r; asm("mov.b64 %0, {%1,%2};" : "=l"(r) : "f"(lo), "f"(hi)); return r;
}
__device__ __forceinline__ void unpack2(u64 v, float& lo, float& hi) {
    asm("mov.b64 {%0,%1}, %2;" : "=f"(lo), "=f"(hi) : "l"(v));
}
__device__ __forceinline__ u64 fma2(u64 a, u64 b, u64 c) {
    u64 d; asm("fma.rn.f32x2 %0, %1, %2, %3;" : "=l"(d) : "l"(a), "l"(b), "l"(c)); return d;
}
__device__ __forceinline__ u64 mul2(u64 a, u64 b) {
    u64 d; asm("mul.rn.f32x2 %0, %1, %2;" : "=l"(d) : "l"(a), "l"(b)); return d;
}

// ================= fp16 NT GEMM via mma.sync ================================
// C[M,N] = A[M,K2] * B[N,K2]^T, fp32 accum.
// CTA tile 128(M) x 128(N), BK=64, 3 stages, 4 warps of 64x64, 128 threads,
// 2 CTAs/SM (measured-best config from R7/R10).
#define STAGES 3
#define A_BYTES 16384                    // 128 x 64 x 2
#define B_BYTES 16384                    // 128 x 64 x 2
#define STAGE_BYTES (A_BYTES + B_BYTES)  // 32KB
#define GEMM_SMEM (STAGES * STAGE_BYTES) // 96KB

__global__ __launch_bounds__(128, 2) void gemm_fp16_mma(
    const __half* __restrict__ A, const __half* __restrict__ Bw,
    float* __restrict__ C, int M, int N, int K2)
{
    extern __shared__ char smem[];
    const uint32_t s_base = smem_to_u32(smem);
    const int tid  = threadIdx.x;
    const int lane = tid & 31;
    const int wid  = tid >> 5;
    const int wm = wid & 1;        // 2 warp-rows (64 M each)
    const int wn = wid >> 1;       // 2 warp-cols (64 N each)
    const int bm = blockIdx.y * 128;
    const int bn = blockIdx.x * 128;

    const int lrow = tid >> 3;     // 0..15
    const int lchk = tid & 7;      // 16B chunk within 128B row
    const __half* Ag = A  + (size_t)(bm + lrow) * K2 + lchk * 8;
    const __half* Bg = Bw + (size_t)(bn + lrow) * K2 + lchk * 8;

    const int nchunks = K2 >> 6;

    float acc[4][8][4];
    #pragma unroll
    for (int i = 0; i < 4; i++)
        #pragma unroll
        for (int j = 0; j < 8; j++)
            #pragma unroll
            for (int k = 0; k < 4; k++) acc[i][j][k] = 0.f;

    const int jm = lane >> 3;
    const int rr = lane & 7;

    // prologue
    #pragma unroll
    for (int s = 0; s < STAGES - 1; s++) {
        const int k0 = s * 64;
        const uint32_t dA = s_base + s * STAGE_BYTES;
        const uint32_t dB = dA + A_BYTES;
        #pragma unroll
        for (int i = 0; i < 8; i++) {
            const int row = lrow + i * 16;
            const uint32_t off = (uint32_t)row * 128 + (uint32_t)((lchk ^ (row & 7)) * 16);
            cp_async16(dA + off, Ag + (size_t)i * 16 * K2 + k0);
            cp_async16(dB + off, Bg + (size_t)i * 16 * K2 + k0);
        }
        CP_COMMIT();
    }

    for (int c = 0; c < nchunks; c++) {
        CP_WAIT1();
        __syncthreads();

        const int nxt = c + STAGES - 1;
        if (nxt < nchunks) {
            const int s = nxt % STAGES;
            const int k0 = nxt * 64;
            const uint32_t dA = s_base + s * STAGE_BYTES;
            const uint32_t dB = dA + A_BYTES;
            #pragma unroll
            for (int i = 0; i < 8; i++) {
                const int row = lrow + i * 16;
                const uint32_t off = (uint32_t)row * 128 + (uint32_t)((lchk ^ (row & 7)) * 16);
                cp_async16(dA + off, Ag + (size_t)i * 16 * K2 + k0);
                cp_async16(dB + off, Bg + (size_t)i * 16 * K2 + k0);
            }
        }
        CP_COMMIT();

        const int s = c % STAGES;
        const uint32_t Ab = s_base + s * STAGE_BYTES;
        const uint32_t Bb = Ab + A_BYTES;
        #pragma unroll
        for (int ks = 0; ks < 4; ks++) {
            const int kc = ks * 2;
            uint32_t af[4][4];
            #pragma unroll
            for (int mi = 0; mi < 4; mi++) {
                const int r  = wm * 64 + mi * 16 + (jm & 1) * 8 + rr;
                const int cc = (kc + (jm >> 1)) ^ (r & 7);
                ldm_x4(af[mi], Ab + (uint32_t)(r * 128 + cc * 16));
            }
            uint32_t bf[4][4];
            #pragma unroll
            for (int nb = 0; nb < 4; nb++) {
                const int r  = wn * 64 + nb * 16 + (jm >> 1) * 8 + rr;
                const int cc = (kc + (jm & 1)) ^ (r & 7);
                ldm_x4(bf[nb], Bb + (uint32_t)(r * 128 + cc * 16));
            }
            #pragma unroll
            for (int mi = 0; mi < 4; mi++)
                #pragma unroll
                for (int ni = 0; ni < 8; ni++)
                    mma16816(acc[mi][ni], af[mi],
                             bf[ni >> 1][(ni & 1) * 2], bf[ni >> 1][(ni & 1) * 2 + 1]);
        }
        // no trailing __syncthreads — top-of-loop barrier orders stage reuse
    }

    // epilogue: fp32 direct store
    #pragma unroll
    for (int mi = 0; mi < 4; mi++) {
        const int row = bm + wm * 64 + mi * 16 + (lane >> 2);
        #pragma unroll
        for (int ni = 0; ni < 8; ni++) {
            const int col = bn + wn * 64 + ni * 8 + (lane & 3) * 2;
            *(float2*)(C + (size_t)row * N + col)       = make_float2(acc[mi][ni][0], acc[mi][ni][1]);
            *(float2*)(C + (size_t)(row + 8) * N + col) = make_float2(acc[mi][ni][2], acc[mi][ni][3]);
        }
    }
}

// ================= fp32 -> fp16x2 split (device body) ======================
// mode 0 (A-side): [hi | lo]   mode 1 (B-side): [hi | hi]
__device__ __forceinline__ uint2 packh4(float a, float b, float c, float d) {
    __half2 lo = __floats2half2_rn(a, b);
    __half2 hi = __floats2half2_rn(c, d);
    uint2 r; r.x = *(uint32_t*)&lo; r.y = *(uint32_t*)&hi; return r;
}
__device__ __forceinline__ void split_one(const float* __restrict__ src,
                                          __half* __restrict__ dst,
                                          int K, int mode, size_t i4)
{
    size_t idx = i4 * 4;
    int row = (int)(idx / K);
    int k   = (int)(idx % K);
    float4 v = *(const float4*)(src + idx);
    __half h0 = __float2half_rn(v.x), h1 = __float2half_rn(v.y);
    __half h2 = __float2half_rn(v.z), h3 = __float2half_rn(v.w);
    uint2 hp; hp.x = (uint32_t)*(uint16_t*)&h0 | ((uint32_t)*(uint16_t*)&h1 << 16);
    hp.y = (uint32_t)*(uint16_t*)&h2 | ((uint32_t)*(uint16_t*)&h3 << 16);
    __half* base = dst + (size_t)row * 2 * K;
    *(uint2*)(base + k) = hp;
    if (mode == 0) {
        uint2 lp = packh4(v.x - __half2float(h0), v.y - __half2float(h1),
                          v.z - __half2float(h2), v.w - __half2float(h3));
        *(uint2*)(base + K + k) = lp;
    } else {
        *(uint2*)(base + K + k) = hp;
    }
}

// ----- ONE prep launch: x split + 3 weight splits + wba build --------------
#define PN0 ((size_t)BT_  * HID_ / 4)          // x
#define PN1 (PN0 + (size_t)QKV_ * HID_ / 4)    // W_qkv
#define PN2 (PN1 + (size_t)VD_  * HID_ / 4)    // W_z
#define PN3 (PN2 + (size_t)HID_ * VD_  / 4)    // W_out
#define PN4 (PN3 + (size_t)256  * HID_ / 4)    // W_ba pad  (total 10,616,832)

__global__ void prep_kernel(const float* __restrict__ x,  const float* __restrict__ Wq,
                            const float* __restrict__ Wz, const float* __restrict__ Wo,
                            const float* __restrict__ Wb, const float* __restrict__ Wa)
{
    size_t i4 = (size_t)blockIdx.x * blockDim.x + threadIdx.x;
    if (i4 < PN0) { split_one(x, g_x2, HID_, 0, i4); return; }
    if (i4 < PN1) { split_one(Wq, g_wq2, HID_, 1, i4 - PN0); return; }
    if (i4 < PN2) { split_one(Wz, g_wzba2, HID_, 1, i4 - PN1); return; }
    if (i4 < PN3) { split_one(Wo, g_wo2, VD_, 1, i4 - PN2); return; }
    // W_ba padded rows into g_wzba2 at row offset VD_
    size_t r4 = i4 - PN3;
    size_t idx = r4 * 4;
    int row = (int)(idx / HID_);
    int k   = (int)(idx % HID_);
    float4 v = make_float4(0.f, 0.f, 0.f, 0.f);
    if (row < 32)      v = *(const float4*)(Wb + (size_t)row * HID_ + k);
    else if (row < 64) v = *(const float4*)(Wa + (size_t)(row - 32) * HID_ + k);
    __half h0 = __float2half_rn(v.x), h1 = __float2half_rn(v.y);
    __half h2 = __float2half_rn(v.z), h3 = __float2half_rn(v.w);
    uint2 hp; hp.x = (uint32_t)*(uint16_t*)&h0 | ((uint32_t)*(uint16_t*)&h1 << 16);
    hp.y = (uint32_t)*(uint16_t*)&h2 | ((uint32_t)*(uint16_t*)&h3 << 16);
    __half* base = g_wzba2 + ((size_t)VD_ + row) * 2 * HID_;
    *(uint2*)(base + k)        = hp;
    *(uint2*)(base + HID_ + k) = hp;
}

// beta/decay activations from combined z|ba buffer (cols VD_.., stride NZB_)
__global__ void act_ba_kernel(const float* __restrict__ dt_bias, const float* __restrict__ A_log)
{
    int idx = blockIdx.x * blockDim.x + threadIdx.x;
    if (idx >= BT_ * NV_) return;
    int row = idx / NV_, nv = idx % NV_;
    float sb = g_zba[(size_t)row * NZB_ + VD_ + nv];
    float sa = g_zba[(size_t)row * NZB_ + VD_ + 32 + nv];
    g_beta[idx] = 1.f / (1.f + expf(-sb));
    float aa = sa + dt_bias[nv];
    float sp = (aa > 20.f) ? aa : log1pf(expf(aa));
    g_decay[idx] = expf(-sp * expf(A_log[nv]));
}

// ---------- causal depthwise conv: 4 channels x 4 timesteps per thread -----
__global__ void conv_kernel(const float* __restrict__ cw)
{
    const int NC4 = QKV_ / 4;   // 2048
    const int NT4 = T_ / 4;     // 512
    int idx = blockIdx.x * blockDim.x + threadIdx.x;
    if (idx >= B_ * NT4 * NC4) return;
    const int c4 = idx % NC4;
    const int tmp = idx / NC4;
    const int t4 = tmp % NT4;
    const int b  = tmp / NT4;
    const int t0 = t4 * 4;
    const int c0 = c4 * 4;

    float4 w[4];
    #pragma unroll
    for (int ch = 0; ch < 4; ch++) w[ch] = *(const float4*)(cw + (size_t)(c0 + ch) * 4);

    const float* base = g_qkv + ((size_t)b * T_ + t0) * QKV_ + c0;
    float4 xv[7];
    #pragma unroll
    for (int d = 0; d < 7; d++) {
        const int t = t0 - 3 + d;
        xv[d] = (t >= 0) ? *(const float4*)(base + (ptrdiff_t)(d - 3) * QKV_)
                         : make_float4(0.f, 0.f, 0.f, 0.f);
    }
    float* outb = g_qkvc + ((size_t)b * T_ + t0) * QKV_ + c0;
    #pragma unroll
    for (int s = 0; s < 4; s++) {
        float4 y;
        y.x = xv[s].x*w[0].x + xv[s+1].x*w[0].y + xv[s+2].x*w[0].z + xv[s+3].x*w[0].w;
        y.y = xv[s].y*w[1].x + xv[s+1].y*w[1].y + xv[s+2].y*w[1].z + xv[s+3].y*w[1].w;
        y.z = xv[s].z*w[2].x + xv[s+1].z*w[2].y + xv[s+2].z*w[2].z + xv[s+3].z*w[2].w;
        y.w = xv[s].w*w[3].x + xv[s+1].w*w[3].y + xv[s+2].w*w[3].z + xv[s+3].w*w[3].w;
        *(float4*)(outb + (size_t)s * QKV_) = y;
    }
}

// ---------------- new_conv_buf: raw qkv rows T-3..T-1, transposed ----------
__global__ void convbuf_kernel(float* __restrict__ buf)
{
    int idx = blockIdx.x * blockDim.x + threadIdx.x;
    if (idx >= B_ * QKV_ * (KC_-1)) return;
    const int j = idx % (KC_-1);
    const int c = (idx / (KC_-1)) % QKV_;
    const int b = idx / ((KC_-1) * QKV_);
    buf[idx] = g_qkv[((size_t)(b * T_ + (T_ - (KC_-1) + j))) * QKV_ + c];
}

// ---------------- l2 normalize q and k heads (in place) --------------------
__global__ void l2norm_kernel()
{
    const int w = (blockIdx.x * blockDim.x + threadIdx.x) >> 5;
    const int lane = threadIdx.x & 31;
    if (w >= BT_ * 2 * NK_) return;
    const int h = w % (2 * NK_);
    const size_t bt = (size_t)(w / (2 * NK_));
    float* base = g_qkvc + bt * QKV_ + (size_t)h * DK_;
    float4 v = *(float4*)(base + lane * 4);
    float s = v.x*v.x + v.y*v.y + v.z*v.z + v.w*v.w;
    #pragma unroll
    for (int o = 16; o; o >>= 1) s += __shfl_xor_sync(0xffffffffu, s, o);
    const float inv = 1.f / fmaxf(sqrtf(s), 1e-12f);
    v.x *= inv; v.y *= inv; v.z *= inv; v.w *= inv;
    *(float4*)(base + lane * 4) = v;
}

// ---- sequential gated delta-rule scan (deferred decay, f32x2, col-split x2)
// 128 CTAs: CTA = (b, nv, half). 128 threads: pair (jloc, h) — thread owns
// rows h*64..h*64+63 (as 32 f32x2 pairs) of column j = half*64 + jloc.
// Vectorized smem loads: k/q fetched as ulonglong2 (LDS.128), halving LDS issues.
__global__ __launch_bounds__(128, 1) void scan_kernel(float* __restrict__ s_final)
{
    const int bx   = blockIdx.x;
    const int half = bx & 1;
    const int bnv  = bx >> 1;
    const int b  = bnv / NV_;
    const int nv = bnv % NV_;
    const int nk = nv >> 1;
    const int p  = nv & 1;
    const int tid  = threadIdx.x;
    const int jloc = tid >> 1;
    const int h    = tid & 1;
    const int j    = half * 64 + jloc;
    const int hoff = h * 64;

    u64 Sa[32];
    #pragma unroll
    for (int i = 0; i < 32; i++) Sa[i] = 0ull;
    float D = 1.f;

    __shared__ __align__(16) float qs[2][128];
    __shared__ __align__(16) float ks[2][128];

    const float* base = g_qkvc + (size_t)b * T_ * QKV_;
    const int row0 = b * T_;

    // prologue: t = 0
    qs[0][tid] = base[nk * DK_ + tid];
    ks[0][tid] = base[QD_ + nk * DK_ + tid];
    float v  = base[2 * QD_ + nv * DV_ + j];
    float be = g_beta [row0 * NV_ + nv];
    float de = g_decay[row0 * NV_ + nv];
    __syncthreads();

    for (int t = 0; t < T_; t++) {
        // prefetch t+1 into registers (LDG hidden under compute)
        float qn = 0.f, kn = 0.f, vn = 0.f, ben = 0.f, den = 0.f;
        if (t + 1 < T_) {
            const float* rown = base + (size_t)(t + 1) * QKV_;
            qn  = rown[nk * DK_ + tid];
            kn  = rown[QD_ + nk * DK_ + tid];
            vn  = rown[2 * QD_ + nv * DV_ + j];
            ben = g_beta [(row0 + t + 1) * NV_ + nv];
            den = g_decay[(row0 + t + 1) * NV_ + nv];
        }
        const int buf = t & 1;
        const ulonglong2* k4v = (const ulonglong2*)(ks[buf] + hoff);
        const ulonglong2* q4v = (const ulonglong2*)(qs[buf] + hoff);

        // vectorized k load: 16 x LDS.128
        u64 kk[32];
        #pragma unroll
        for (int i = 0; i < 16; i++) {
            ulonglong2 tk = k4v[i];
            kk[2*i]   = tk.x;
            kk[2*i+1] = tk.y;
        }

        // partial sk = k[h-rows] . Sa  (packed); true sk = D * total
        u64 a0 = 0ull, a1 = 0ull, a2 = 0ull, a3 = 0ull;
        #pragma unroll
        for (int i = 0; i < 32; i += 4) {
            a0 = fma2(kk[i+0], Sa[i+0], a0);
            a1 = fma2(kk[i+1], Sa[i+1], a1);
            a2 = fma2(kk[i+2], Sa[i+2], a2);
            a3 = fma2(kk[i+3], Sa[i+3], a3);
        }
        float x0, x1, x2, x3, x4, x5, x6, x7;
        unpack2(a0, x0, x1); unpack2(a1, x2, x3);
        unpack2(a2, x4, x5); unpack2(a3, x6, x7);
        float skp = ((x0 + x1) + (x2 + x3)) + ((x4 + x5) + (x6 + x7));
        skp += __shfl_xor_sync(0xffffffffu, skp, 1);
        const float sk = D * skp;
        const float dv = be * (v - sk);
        const float Dn = D * de;

        // S_true_new = Dn * Sa_new
        u64 o0 = 0ull, o1 = 0ull, o2 = 0ull, o3 = 0ull;
        float o_scale;
        if (Dn >= 1e-12f) {
            // normal: Sa += (dv/Dn) * k   (1 fma2/pair); q via LDS.128
            const float c = __fdividef(dv, Dn);
            const u64 c2 = pack2(c, c);
            #pragma unroll
            for (int i = 0; i < 32; i += 4) {
                ulonglong2 qa = q4v[i >> 1];
                ulonglong2 qb = q4v[(i >> 1) + 1];
                Sa[i+0] = fma2(c2, kk[i+0], Sa[i+0]);  o0 = fma2(qa.x, Sa[i+0], o0);
                Sa[i+1] = fma2(c2, kk[i+1], Sa[i+1]);  o1 = fma2(qa.y, Sa[i+1], o1);
                Sa[i+2] = fma2(c2, kk[i+2], Sa[i+2]);  o2 = fma2(qb.x, Sa[i+2], o2);
                Sa[i+3] = fma2(c2, kk[i+3], Sa[i+3]);  o3 = fma2(qb.y, Sa[i+3], o3);
            }
            D = Dn;
            o_scale = Dn;
        } else {
            // renormalize: Sa = Dn*Sa + dv*k ; D = 1
            const u64 s2  = pack2(Dn, Dn);
            const u64 dv2 = pack2(dv, dv);
            #pragma unroll
            for (int i = 0; i < 32; i += 4) {
                ulonglong2 qa = q4v[i >> 1];
                ulonglong2 qb = q4v[(i >> 1) + 1];
                Sa[i+0] = fma2(s2, Sa[i+0], mul2(dv2, kk[i+0]));  o0 = fma2(qa.x, Sa[i+0], o0);
                Sa[i+1] = fma2(s2, Sa[i+1], mul2(dv2, kk[i+1]));  o1 = fma2(qa.y, Sa[i+1], o1);
                Sa[i+2] = fma2(s2, Sa[i+2], mul2(dv2, kk[i+2]));  o2 = fma2(qb.x, Sa[i+2], o2);
                Sa[i+3] = fma2(s2, Sa[i+3], mul2(dv2, kk[i+3]));  o3 = fma2(qb.y, Sa[i+3], o3);
            }
            D = 1.f;
            o_scale = 1.f;
        }
        unpack2(o0, x0, x1); unpack2(o1, x2, x3);
        unpack2(o2, x4, x5); unpack2(o3, x6, x7);
        float op = ((x0 + x1) + (x2 + x3)) + ((x4 + x5) + (x6 + x7));
        op += __shfl_xor_sync(0xffffffffu, op, 1);
        if (h == 0)
            g_att[((size_t)(row0 + t) * NV_ + nv) * DV_ + j] = o_scale * op;

        // stage t+1 into alternate buffer
        if (t + 1 < T_) {
            qs[buf ^ 1][tid] = qn;
            ks[buf ^ 1][tid] = kn;
        }
        v = vn; be = ben; de = den;
        __syncthreads();
    }

    // S_final [B, NK, DK, P*DV] = D * Sa
    #pragma unroll
    for (int i = 0; i < 32; i++) {
        float lo, hi;
        unpack2(Sa[i], lo, hi);
        const size_t rbase = (((size_t)b * NK_ + nk) * DK_ + (hoff + 2 * i));
        s_final[(rbase * P_ + p) * DV_ + j]         = D * lo;
        s_final[((rbase + 1) * P_ + p) * DV_ + j]   = D * hi;
    }
}

// ------- RMSNorm + SiLU gate, fused with fp16x2 A-side split ---------------
// z read from combined z|ba buffer (cols 0..VD_-1, row stride NZB_).
__global__ void rmsgate_split_kernel(const float* __restrict__ norm_w)
{
    const int w = (blockIdx.x * blockDim.x + threadIdx.x) >> 5;
    const int lane = threadIdx.x & 31;
    if (w >= BT_ * NV_) return;
    const size_t off = (size_t)w * DV_ + lane * 4;
    float4 o = *(float4*)(g_att + off);
    float ss = o.x*o.x + o.y*o.y + o.z*o.z + o.w*o.w;
    #pragma unroll
    for (int k = 16; k; k >>= 1) ss += __shfl_xor_sync(0xffffffffu, ss, k);
    const float r = rsqrtf(ss * (1.f / DV_) + 1e-6f);
    const int bt = w / NV_;
    const int k  = (w % NV_) * DV_ + lane * 4;
    float4 z  = *(float4*)(g_zba + (size_t)bt * NZB_ + k);
    float4 nw = *(const float4*)(norm_w + lane * 4);
    float4 g;
    g.x = o.x * r * nw.x * (z.x / (1.f + expf(-z.x)));
    g.y = o.y * r * nw.y * (z.y / (1.f + expf(-z.y)));
    g.z = o.z * r * nw.z * (z.z / (1.f + expf(-z.z)));
    g.w = o.w * r * nw.w * (z.w / (1.f + expf(-z.w)));

    __half h0 = __float2half_rn(g.x), h1 = __float2half_rn(g.y);
    __half h2 = __float2half_rn(g.z), h3 = __float2half_rn(g.w);
    uint2 hp; hp.x = (uint32_t)*(uint16_t*)&h0 | ((uint32_t)*(uint16_t*)&h1 << 16);
    hp.y = (uint32_t)*(uint16_t*)&h2 | ((uint32_t)*(uint16_t*)&h3 << 16);
    uint2 lp = packh4(g.x - __half2float(h0), g.y - __half2float(h1),
                      g.z - __half2float(h2), g.w - __half2float(h3));
    __half* base = g_att2 + (size_t)bt * 2 * VD_;
    *(uint2*)(base + k)       = hp;
    *(uint2*)(base + VD_ + k) = lp;
}

// ---------------- launch ----------------------------------------------------
extern "C" void kernel_launch(void* const* d_in, const int* in_sizes, int n_in,
                              void* d_out, int out_size)
{
    const float* x       = (const float*)d_in[0];
    const float* W_qkv   = (const float*)d_in[1];
    const float* W_z     = (const float*)d_in[2];
    const float* W_b     = (const float*)d_in[3];
    const float* W_a     = (const float*)d_in[4];
    const float* conv_w  = (const float*)d_in[5];
    const float* dt_bias = (const float*)d_in[6];
    const float* A_log   = (const float*)d_in[7];
    const float* norm_w  = (const float*)d_in[8];
    const float* W_out   = (const float*)d_in[9];

    float* out      = (float*)d_out;
    float* y        = out;
    float* s_final  = y + (size_t)BT_ * HID_;
    float* conv_buf = s_final + (size_t)B_ * NK_ * DK_ * SV_;

    void* p;
    cudaGetSymbolAddress(&p, g_qkv);   float* qkv  = (float*)p;
    cudaGetSymbolAddress(&p, g_zba);   float* zba  = (float*)p;
    cudaGetSymbolAddress(&p, g_x2);    __half* x2    = (__half*)p;
    cudaGetSymbolAddress(&p, g_wq2);   __half* wq2   = (__half*)p;
    cudaGetSymbolAddress(&p, g_wzba2); __half* wzba2 = (__half*)p;
    cudaGetSymbolAddress(&p, g_wo2);   __half* wo2   = (__half*)p;
    cudaGetSymbolAddress(&p, g_att2);  __half* att2  = (__half*)p;

    cudaFuncSetAttribute(gemm_fp16_mma, cudaFuncAttributeMaxDynamicSharedMemorySize, GEMM_SMEM);

    // 0. single prep launch: x split + weight splits + wba build
    prep_kernel<<<(int)(PN4 / 256), 256>>>(x, W_qkv, W_z, W_out, W_b, W_a);

    // 1. projections on tensor cores (K' = 2K); z+ba fused (N=4352)
    gemm_fp16_mma<<<dim3(QKV_/128, BT_/128), 128, GEMM_SMEM>>>(x2, wq2, qkv, BT_, QKV_, 2*HID_);
    gemm_fp16_mma<<<dim3(NZB_/128, BT_/128), 128, GEMM_SMEM>>>(x2, wzba2, zba, BT_, NZB_, 2*HID_);
    act_ba_kernel<<<(BT_*NV_ + 255)/256, 256>>>(dt_bias, A_log);

    // 2. conv + conv buffer output
    conv_kernel<<<(B_*(T_/4)*(QKV_/4) + 255)/256, 256>>>(conv_w);
    convbuf_kernel<<<(B_*QKV_*(KC_-1) + 255)/256, 256>>>(conv_buf);

    // 3. l2 normalize q,k heads in place
    l2norm_kernel<<<(BT_*2*NK_*32 + 255)/256, 256>>>();

    // 4. sequential scan (also emits S_final)
    scan_kernel<<<2*B_*NV_, 128>>>(s_final);

    // 5. RMSNorm + SiLU gate + fp16x2 split
    rmsgate_split_kernel<<<(BT_*NV_*32 + 255)/256, 256>>>(norm_w);

    // 6. output projection -> y
    gemm_fp16_mma<<<dim3(HID_/128, BT_/128), 128, GEMM_SMEM>>>(att2, wo2, y, BT_, HID_, 2*VD_);
}

// round 16
// speedup vs baseline: 1.0099x; 1.0099x over previous
#include <cuda_runtime.h>
#include <cuda_bf16.h>
#include <cuda_fp16.h>
#include <cstdint>
#include <math.h>

#define B_   2
#define T_   2048
#define HID_ 2048
#define NK_  16
#define DK_  128
#define NV_  32
#define DV_  128
#define KC_  4
#define P_   2
#define QD_  (NK_*DK_)        // 2048
#define VD_  (NV_*DV_)        // 4096
#define QKV_ (2*QD_+VD_)      // 8192
#define SV_  (P_*DV_)         // 256
#define BT_  (B_*T_)          // 4096
#define NZB_ (VD_ + 256)      // 4352 combined (z | ba-pad)

typedef unsigned long long u64;

// ---------------- scratch (device globals; no allocation allowed) ----------
__device__ __align__(16) float g_qkv [(size_t)BT_ * QKV_];   // raw qkv projection
__device__ __align__(16) float g_qkvc[(size_t)BT_ * QKV_];   // post-conv
__device__ __align__(16) float g_zba [(size_t)BT_ * NZB_];   // z | beta/dt pre-activation
__device__ __align__(16) float g_att [(size_t)BT_ * VD_];    // scan output
__device__ float g_beta [BT_ * NV_];
__device__ float g_decay[BT_ * NV_];

// fp16x2 split operands (K' = 2K):  A-side [hi|lo], B-side [hi|hi]
__device__ __align__(16) __half g_x2   [(size_t)BT_  * 2 * HID_];
__device__ __align__(16) __half g_wq2  [(size_t)QKV_ * 2 * HID_];
__device__ __align__(16) __half g_wzba2[(size_t)NZB_ * 2 * HID_];  // W_z | W_ba(pad)
__device__ __align__(16) __half g_wo2  [(size_t)HID_ * 2 * VD_];
__device__ __align__(16) __half g_att2 [(size_t)BT_  * 2 * VD_];

// ================= PTX helpers ==============================================
__device__ __forceinline__ uint32_t smem_to_u32(const void* p) {
    uint32_t a;
    asm("{ .reg .u64 t; cvta.to.shared.u64 t, %1; cvt.u32.u64 %0, t; }" : "=r"(a) : "l"(p));
    return a;
}
__device__ __forceinline__ void cp_async16(uint32_t dst, const void* src) {
    asm volatile("cp.async.cg.shared.global [%0], [%1], 16;" :: "r"(dst), "l"(src) : "memory");
}
#define CP_COMMIT() asm volatile("cp.async.commit_group;" ::: "memory")
#define CP_WAIT1()  asm volatile("cp.async.wait_group 1;"  ::: "memory")

__device__ __forceinline__ void ldm_x4(uint32_t* r, uint32_t a) {
    asm volatile("ldmatrix.sync.aligned.m8n8.x4.shared.b16 {%0,%1,%2,%3}, [%4];"
        : "=r"(r[0]), "=r"(r[1]), "=r"(r[2]), "=r"(r[3]) : "r"(a));
}
__device__ __forceinline__ void mma16816(float* d, const uint32_t* a, uint32_t b0, uint32_t b1) {
    asm volatile("mma.sync.aligned.m16n8k16.row.col.f32.f16.f16.f32 "
        "{%0,%1,%2,%3}, {%4,%5,%6,%7}, {%8,%9}, {%0,%1,%2,%3};"
        : "+f"(d[0]), "+f"(d[1]), "+f"(d[2]), "+f"(d[3])
        : "r"(a[0]), "r"(a[1]), "r"(a[2]), "r"(a[3]), "r"(b0), "r"(b1));
}

// packed fp32x2 (Blackwell)
__device__ __forceinline__ u64 pack2(float lo, float hi) {
    u64 r; asm("mov.b64 %0, {%1,%2};" : "=l"(r) : "f"(lo), "f"(hi)); return r;
}
__device__ __forceinline__ void unpack2(u64 v, float& lo, float& hi) {
    asm("mov.b64 {%0,%1}, %2;" : "=f"(lo), "=f"(hi) : "l"(v));
}
__device__ __forceinline__ u64 fma2(u64 a, u64 b, u64 c) {
    u64 d; asm("fma.rn.f32x2 %0, %1, %2, %3;" : "=l"(d) : "l"(a), "l"(b), "l"(c)); return d;
}
__device__ __forceinline__ u64 mul2(u64 a, u64 b) {
    u64 d; asm("mul.rn.f32x2 %0, %1, %2;" : "=l"(d) : "l"(a), "l"(b)); return d;
}

// ================= fp16 NT GEMM via mma.sync ================================
// C[M,N] = A[M,K2] * B[N,K2]^T, fp32 accum.
// CTA tile 128(M) x 128(N), BK=64, 3 stages, 4 warps of 64x64, 128 threads,
// 2 CTAs/SM (measured-best config from R7/R10).
#define STAGES 3
#define A_BYTES 16384                    // 128 x 64 x 2
#define B_BYTES 16384                    // 128 x 64 x 2
#define STAGE_BYTES (A_BYTES + B_BYTES)  // 32KB
#define GEMM_SMEM (STAGES * STAGE_BYTES) // 96KB

__global__ __launch_bounds__(128, 2) void gemm_fp16_mma(
    const __half* __restrict__ A, const __half* __restrict__ Bw,
    float* __restrict__ C, int M, int N, int K2)
{
    extern __shared__ char smem[];
    const uint32_t s_base = smem_to_u32(smem);
    const int tid  = threadIdx.x;
    const int lane = tid & 31;
    const int wid  = tid >> 5;
    const int wm = wid & 1;        // 2 warp-rows (64 M each)
    const int wn = wid >> 1;       // 2 warp-cols (64 N each)
    const int bm = blockIdx.y * 128;
    const int bn = blockIdx.x * 128;

    const int lrow = tid >> 3;     // 0..15
    const int lchk = tid & 7;      // 16B chunk within 128B row
    const __half* Ag = A  + (size_t)(bm + lrow) * K2 + lchk * 8;
    const __half* Bg = Bw + (size_t)(bn + lrow) * K2 + lchk * 8;

    const int nchunks = K2 >> 6;

    float acc[4][8][4];
    #pragma unroll
    for (int i = 0; i < 4; i++)
        #pragma unroll
        for (int j = 0; j < 8; j++)
            #pragma unroll
            for (int k = 0; k < 4; k++) acc[i][j][k] = 0.f;

    const int jm = lane >> 3;
    const int rr = lane & 7;

    // prologue
    #pragma unroll
    for (int s = 0; s < STAGES - 1; s++) {
        const int k0 = s * 64;
        const uint32_t dA = s_base + s * STAGE_BYTES;
        const uint32_t dB = dA + A_BYTES;
        #pragma unroll
        for (int i = 0; i < 8; i++) {
            const int row = lrow + i * 16;
            const uint32_t off = (uint32_t)row * 128 + (uint32_t)((lchk ^ (row & 7)) * 16);
            cp_async16(dA + off, Ag + (size_t)i * 16 * K2 + k0);
            cp_async16(dB + off, Bg + (size_t)i * 16 * K2 + k0);
        }
        CP_COMMIT();
    }

    for (int c = 0; c < nchunks; c++) {
        CP_WAIT1();
        __syncthreads();

        const int nxt = c + STAGES - 1;
        if (nxt < nchunks) {
            const int s = nxt % STAGES;
            const int k0 = nxt * 64;
            const uint32_t dA = s_base + s * STAGE_BYTES;
            const uint32_t dB = dA + A_BYTES;
            #pragma unroll
            for (int i = 0; i < 8; i++) {
                const int row = lrow + i * 16;
                const uint32_t off = (uint32_t)row * 128 + (uint32_t)((lchk ^ (row & 7)) * 16);
                cp_async16(dA + off, Ag + (size_t)i * 16 * K2 + k0);
                cp_async16(dB + off, Bg + (size_t)i * 16 * K2 + k0);
            }
        }
        CP_COMMIT();

        const int s = c % STAGES;
        const uint32_t Ab = s_base + s * STAGE_BYTES;
        const uint32_t Bb = Ab + A_BYTES;
        #pragma unroll
        for (int ks = 0; ks < 4; ks++) {
            const int kc = ks * 2;
            uint32_t af[4][4];
            #pragma unroll
            for (int mi = 0; mi < 4; mi++) {
                const int r  = wm * 64 + mi * 16 + (jm & 1) * 8 + rr;
                const int cc = (kc + (jm >> 1)) ^ (r & 7);
                ldm_x4(af[mi], Ab + (uint32_t)(r * 128 + cc * 16));
            }
            uint32_t bf[4][4];
            #pragma unroll
            for (int nb = 0; nb < 4; nb++) {
                const int r  = wn * 64 + nb * 16 + (jm >> 1) * 8 + rr;
                const int cc = (kc + (jm & 1)) ^ (r & 7);
                ldm_x4(bf[nb], Bb + (uint32_t)(r * 128 + cc * 16));
            }
            #pragma unroll
            for (int mi = 0; mi < 4; mi++)
                #pragma unroll
                for (int ni = 0; ni < 8; ni++)
                    mma16816(acc[mi][ni], af[mi],
                             bf[ni >> 1][(ni & 1) * 2], bf[ni >> 1][(ni & 1) * 2 + 1]);
        }
        // no trailing __syncthreads — top-of-loop barrier orders stage reuse
    }

    // epilogue: fp32 direct store
    #pragma unroll
    for (int mi = 0; mi < 4; mi++) {
        const int row = bm + wm * 64 + mi * 16 + (lane >> 2);
        #pragma unroll
        for (int ni = 0; ni < 8; ni++) {
            const int col = bn + wn * 64 + ni * 8 + (lane & 3) * 2;
            *(float2*)(C + (size_t)row * N + col)       = make_float2(acc[mi][ni][0], acc[mi][ni][1]);
            *(float2*)(C + (size_t)(row + 8) * N + col) = make_float2(acc[mi][ni][2], acc[mi][ni][3]);
        }
    }
}

// ================= fp32 -> fp16x2 split (device body) ======================
// mode 0 (A-side): [hi | lo]   mode 1 (B-side): [hi | hi]
__device__ __forceinline__ uint2 packh4(float a, float b, float c, float d) {
    __half2 lo = __floats2half2_rn(a, b);
    __half2 hi = __floats2half2_rn(c, d);
    uint2 r; r.x = *(uint32_t*)&lo; r.y = *(uint32_t*)&hi; return r;
}
__device__ __forceinline__ void split_one(const float* __restrict__ src,
                                          __half* __restrict__ dst,
                                          int K, int mode, size_t i4)
{
    size_t idx = i4 * 4;
    int row = (int)(idx / K);
    int k   = (int)(idx % K);
    float4 v = *(const float4*)(src + idx);
    __half h0 = __float2half_rn(v.x), h1 = __float2half_rn(v.y);
    __half h2 = __float2half_rn(v.z), h3 = __float2half_rn(v.w);
    uint2 hp; hp.x = (uint32_t)*(uint16_t*)&h0 | ((uint32_t)*(uint16_t*)&h1 << 16);
    hp.y = (uint32_t)*(uint16_t*)&h2 | ((uint32_t)*(uint16_t*)&h3 << 16);
    __half* base = dst + (size_t)row * 2 * K;
    *(uint2*)(base + k) = hp;
    if (mode == 0) {
        uint2 lp = packh4(v.x - __half2float(h0), v.y - __half2float(h1),
                          v.z - __half2float(h2), v.w - __half2float(h3));
        *(uint2*)(base + K + k) = lp;
    } else {
        *(uint2*)(base + K + k) = hp;
    }
}

// ----- ONE prep launch: x split + 3 weight splits + wba build --------------
#define PN0 ((size_t)BT_  * HID_ / 4)          // x
#define PN1 (PN0 + (size_t)QKV_ * HID_ / 4)    // W_qkv
#define PN2 (PN1 + (size_t)VD_  * HID_ / 4)    // W_z
#define PN3 (PN2 + (size_t)HID_ * VD_  / 4)    // W_out
#define PN4 (PN3 + (size_t)256  * HID_ / 4)    // W_ba pad  (total 10,616,832)

__global__ void prep_kernel(const float* __restrict__ x,  const float* __restrict__ Wq,
                            const float* __restrict__ Wz, const float* __restrict__ Wo,
                            const float* __restrict__ Wb, const float* __restrict__ Wa)
{
    size_t i4 = (size_t)blockIdx.x * blockDim.x + threadIdx.x;
    if (i4 < PN0) { split_one(x, g_x2, HID_, 0, i4); return; }
    if (i4 < PN1) { split_one(Wq, g_wq2, HID_, 1, i4 - PN0); return; }
    if (i4 < PN2) { split_one(Wz, g_wzba2, HID_, 1, i4 - PN1); return; }
    if (i4 < PN3) { split_one(Wo, g_wo2, VD_, 1, i4 - PN2); return; }
    // W_ba padded rows into g_wzba2 at row offset VD_
    size_t r4 = i4 - PN3;
    size_t idx = r4 * 4;
    int row = (int)(idx / HID_);
    int k   = (int)(idx % HID_);
    float4 v = make_float4(0.f, 0.f, 0.f, 0.f);
    if (row < 32)      v = *(const float4*)(Wb + (size_t)row * HID_ + k);
    else if (row < 64) v = *(const float4*)(Wa + (size_t)(row - 32) * HID_ + k);
    __half h0 = __float2half_rn(v.x), h1 = __float2half_rn(v.y);
    __half h2 = __float2half_rn(v.z), h3 = __float2half_rn(v.w);
    uint2 hp; hp.x = (uint32_t)*(uint16_t*)&h0 | ((uint32_t)*(uint16_t*)&h1 << 16);
    hp.y = (uint32_t)*(uint16_t*)&h2 | ((uint32_t)*(uint16_t*)&h3 << 16);
    __half* base = g_wzba2 + ((size_t)VD_ + row) * 2 * HID_;
    *(uint2*)(base + k)        = hp;
    *(uint2*)(base + HID_ + k) = hp;
}

// beta/decay activations from combined z|ba buffer (cols VD_.., stride NZB_)
__global__ void act_ba_kernel(const float* __restrict__ dt_bias, const float* __restrict__ A_log)
{
    int idx = blockIdx.x * blockDim.x + threadIdx.x;
    if (idx >= BT_ * NV_) return;
    int row = idx / NV_, nv = idx % NV_;
    float sb = g_zba[(size_t)row * NZB_ + VD_ + nv];
    float sa = g_zba[(size_t)row * NZB_ + VD_ + 32 + nv];
    g_beta[idx] = 1.f / (1.f + expf(-sb));
    float aa = sa + dt_bias[nv];
    float sp = (aa > 20.f) ? aa : log1pf(expf(aa));
    g_decay[idx] = expf(-sp * expf(A_log[nv]));
}

// ---------- causal depthwise conv: 4 channels x 4 timesteps per thread -----
__global__ void conv_kernel(const float* __restrict__ cw)
{
    const int NC4 = QKV_ / 4;   // 2048
    const int NT4 = T_ / 4;     // 512
    int idx = blockIdx.x * blockDim.x + threadIdx.x;
    if (idx >= B_ * NT4 * NC4) return;
    const int c4 = idx % NC4;
    const int tmp = idx / NC4;
    const int t4 = tmp % NT4;
    const int b  = tmp / NT4;
    const int t0 = t4 * 4;
    const int c0 = c4 * 4;

    float4 w[4];
    #pragma unroll
    for (int ch = 0; ch < 4; ch++) w[ch] = *(const float4*)(cw + (size_t)(c0 + ch) * 4);

    const float* base = g_qkv + ((size_t)b * T_ + t0) * QKV_ + c0;
    float4 xv[7];
    #pragma unroll
    for (int d = 0; d < 7; d++) {
        const int t = t0 - 3 + d;
        xv[d] = (t >= 0) ? *(const float4*)(base + (ptrdiff_t)(d - 3) * QKV_)
                         : make_float4(0.f, 0.f, 0.f, 0.f);
    }
    float* outb = g_qkvc + ((size_t)b * T_ + t0) * QKV_ + c0;
    #pragma unroll
    for (int s = 0; s < 4; s++) {
        float4 y;
        y.x = xv[s].x*w[0].x + xv[s+1].x*w[0].y + xv[s+2].x*w[0].z + xv[s+3].x*w[0].w;
        y.y = xv[s].y*w[1].x + xv[s+1].y*w[1].y + xv[s+2].y*w[1].z + xv[s+3].y*w[1].w;
        y.z = xv[s].z*w[2].x + xv[s+1].z*w[2].y + xv[s+2].z*w[2].z + xv[s+3].z*w[2].w;
        y.w = xv[s].w*w[3].x + xv[s+1].w*w[3].y + xv[s+2].w*w[3].z + xv[s+3].w*w[3].w;
        *(float4*)(outb + (size_t)s * QKV_) = y;
    }
}

// ---------------- new_conv_buf: raw qkv rows T-3..T-1, transposed ----------
__global__ void convbuf_kernel(float* __restrict__ buf)
{
    int idx = blockIdx.x * blockDim.x + threadIdx.x;
    if (idx >= B_ * QKV_ * (KC_-1)) return;
    const int j = idx % (KC_-1);
    const int c = (idx / (KC_-1)) % QKV_;
    const int b = idx / ((KC_-1) * QKV_);
    buf[idx] = g_qkv[((size_t)(b * T_ + (T_ - (KC_-1) + j))) * QKV_ + c];
}

// ---------------- l2 normalize q and k heads (in place) --------------------
__global__ void l2norm_kernel()
{
    const int w = (blockIdx.x * blockDim.x + threadIdx.x) >> 5;
    const int lane = threadIdx.x & 31;
    if (w >= BT_ * 2 * NK_) return;
    const int h = w % (2 * NK_);
    const size_t bt = (size_t)(w / (2 * NK_));
    float* base = g_qkvc + bt * QKV_ + (size_t)h * DK_;
    float4 v = *(float4*)(base + lane * 4);
    float s = v.x*v.x + v.y*v.y + v.z*v.z + v.w*v.w;
    #pragma unroll
    for (int o = 16; o; o >>= 1) s += __shfl_xor_sync(0xffffffffu, s, o);
    const float inv = 1.f / fmaxf(sqrtf(s), 1e-12f);
    v.x *= inv; v.y *= inv; v.z *= inv; v.w *= inv;
    *(float4*)(base + lane * 4) = v;
}

// ---- sequential gated delta-rule scan (deferred decay, f32x2, col-split x2)
// 128 CTAs: CTA = (b, nv, half). 128 threads: pair (jloc, h) — thread owns
// rows h*64..h*64+63 (as 32 f32x2 pairs) of column j = half*64 + jloc.
// R14 form exactly (u64 smem loads; LDS.128 variant regressed in R15).
__global__ __launch_bounds__(128, 1) void scan_kernel(float* __restrict__ s_final)
{
    const int bx   = blockIdx.x;
    const int half = bx & 1;
    const int bnv  = bx >> 1;
    const int b  = bnv / NV_;
    const int nv = bnv % NV_;
    const int nk = nv >> 1;
    const int p  = nv & 1;
    const int tid  = threadIdx.x;
    const int jloc = tid >> 1;
    const int h    = tid & 1;
    const int j    = half * 64 + jloc;
    const int hoff = h * 64;

    u64 Sa[32];
    #pragma unroll
    for (int i = 0; i < 32; i++) Sa[i] = 0ull;
    float D = 1.f;

    __shared__ __align__(16) float qs[2][128];
    __shared__ __align__(16) float ks[2][128];

    const float* base = g_qkvc + (size_t)b * T_ * QKV_;
    const int row0 = b * T_;

    // prologue: t = 0
    qs[0][tid] = base[nk * DK_ + tid];
    ks[0][tid] = base[QD_ + nk * DK_ + tid];
    float v  = base[2 * QD_ + nv * DV_ + j];
    float be = g_beta [row0 * NV_ + nv];
    float de = g_decay[row0 * NV_ + nv];
    __syncthreads();

    for (int t = 0; t < T_; t++) {
        // prefetch t+1 into registers (LDG hidden under compute)
        float qn = 0.f, kn = 0.f, vn = 0.f, ben = 0.f, den = 0.f;
        if (t + 1 < T_) {
            const float* rown = base + (size_t)(t + 1) * QKV_;
            qn  = rown[nk * DK_ + tid];
            kn  = rown[QD_ + nk * DK_ + tid];
            vn  = rown[2 * QD_ + nv * DV_ + j];
            ben = g_beta [(row0 + t + 1) * NV_ + nv];
            den = g_decay[(row0 + t + 1) * NV_ + nv];
        }
        const int buf = t & 1;
        const u64* k2 = (const u64*)(ks[buf] + hoff);
        const u64* q2 = (const u64*)(qs[buf] + hoff);

        u64 kk[32];
        #pragma unroll
        for (int i = 0; i < 32; i++) kk[i] = k2[i];

        // partial sk = k[h-rows] . Sa  (packed); true sk = D * total
        u64 a0 = 0ull, a1 = 0ull, a2 = 0ull, a3 = 0ull;
        #pragma unroll
        for (int i = 0; i < 32; i += 4) {
            a0 = fma2(kk[i+0], Sa[i+0], a0);
            a1 = fma2(kk[i+1], Sa[i+1], a1);
            a2 = fma2(kk[i+2], Sa[i+2], a2);
            a3 = fma2(kk[i+3], Sa[i+3], a3);
        }
        float x0, x1, x2, x3, x4, x5, x6, x7;
        unpack2(a0, x0, x1); unpack2(a1, x2, x3);
        unpack2(a2, x4, x5); unpack2(a3, x6, x7);
        float skp = ((x0 + x1) + (x2 + x3)) + ((x4 + x5) + (x6 + x7));
        skp += __shfl_xor_sync(0xffffffffu, skp, 1);
        const float sk = D * skp;
        const float dv = be * (v - sk);
        const float Dn = D * de;

        // S_true_new = Dn * Sa_new
        u64 o0 = 0ull, o1 = 0ull, o2 = 0ull, o3 = 0ull;
        float o_scale;
        if (Dn >= 1e-12f) {
            // normal: Sa += (dv/Dn) * k   (1 fma2/pair)
            const float c = __fdividef(dv, Dn);
            const u64 c2 = pack2(c, c);
            #pragma unroll
            for (int i = 0; i < 32; i += 4) {
                Sa[i+0] = fma2(c2, kk[i+0], Sa[i+0]);  o0 = fma2(q2[i+0], Sa[i+0], o0);
                Sa[i+1] = fma2(c2, kk[i+1], Sa[i+1]);  o1 = fma2(q2[i+1], Sa[i+1], o1);
                Sa[i+2] = fma2(c2, kk[i+2], Sa[i+2]);  o2 = fma2(q2[i+2], Sa[i+2], o2);
                Sa[i+3] = fma2(c2, kk[i+3], Sa[i+3]);  o3 = fma2(q2[i+3], Sa[i+3], o3);
            }
            D = Dn;
            o_scale = Dn;
        } else {
            // renormalize: Sa = Dn*Sa + dv*k ; D = 1
            const u64 s2  = pack2(Dn, Dn);
            const u64 dv2 = pack2(dv, dv);
            #pragma unroll
            for (int i = 0; i < 32; i += 4) {
                Sa[i+0] = fma2(s2, Sa[i+0], mul2(dv2, kk[i+0]));  o0 = fma2(q2[i+0], Sa[i+0], o0);
                Sa[i+1] = fma2(s2, Sa[i+1], mul2(dv2, kk[i+1]));  o1 = fma2(q2[i+1], Sa[i+1], o1);
                Sa[i+2] = fma2(s2, Sa[i+2], mul2(dv2, kk[i+2]));  o2 = fma2(q2[i+2], Sa[i+2], o2);
                Sa[i+3] = fma2(s2, Sa[i+3], mul2(dv2, kk[i+3]));  o3 = fma2(q2[i+3], Sa[i+3], o3);
            }
            D = 1.f;
            o_scale = 1.f;
        }
        unpack2(o0, x0, x1); unpack2(o1, x2, x3);
        unpack2(o2, x4, x5); unpack2(o3, x6, x7);
        float op = ((x0 + x1) + (x2 + x3)) + ((x4 + x5) + (x6 + x7));
        op += __shfl_xor_sync(0xffffffffu, op, 1);
        if (h == 0)
            g_att[((size_t)(row0 + t) * NV_ + nv) * DV_ + j] = o_scale * op;

        // stage t+1 into alternate buffer
        if (t + 1 < T_) {
            qs[buf ^ 1][tid] = qn;
            ks[buf ^ 1][tid] = kn;
        }
        v = vn; be = ben; de = den;
        __syncthreads();
    }

    // S_final [B, NK, DK, P*DV] = D * Sa
    #pragma unroll
    for (int i = 0; i < 32; i++) {
        float lo, hi;
        unpack2(Sa[i], lo, hi);
        const size_t rbase = (((size_t)b * NK_ + nk) * DK_ + (hoff + 2 * i));
        s_final[(rbase * P_ + p) * DV_ + j]         = D * lo;
        s_final[((rbase + 1) * P_ + p) * DV_ + j]   = D * hi;
    }
}

// ------- RMSNorm + SiLU gate, fused with fp16x2 A-side split ---------------
// z read from combined z|ba buffer (cols 0..VD_-1, row stride NZB_).
__global__ void rmsgate_split_kernel(const float* __restrict__ norm_w)
{
    const int w = (blockIdx.x * blockDim.x + threadIdx.x) >> 5;
    const int lane = threadIdx.x & 31;
    if (w >= BT_ * NV_) return;
    const size_t off = (size_t)w * DV_ + lane * 4;
    float4 o = *(float4*)(g_att + off);
    float ss = o.x*o.x + o.y*o.y + o.z*o.z + o.w*o.w;
    #pragma unroll
    for (int k = 16; k; k >>= 1) ss += __shfl_xor_sync(0xffffffffu, ss, k);
    const float r = rsqrtf(ss * (1.f / DV_) + 1e-6f);
    const int bt = w / NV_;
    const int k  = (w % NV_) * DV_ + lane * 4;
    float4 z  = *(float4*)(g_zba + (size_t)bt * NZB_ + k);
    float4 nw = *(const float4*)(norm_w + lane * 4);
    float4 g;
    g.x = o.x * r * nw.x * (z.x / (1.f + expf(-z.x)));
    g.y = o.y * r * nw.y * (z.y / (1.f + expf(-z.y)));
    g.z = o.z * r * nw.z * (z.z / (1.f + expf(-z.z)));
    g.w = o.w * r * nw.w * (z.w / (1.f + expf(-z.w)));

    __half h0 = __float2half_rn(g.x), h1 = __float2half_rn(g.y);
    __half h2 = __float2half_rn(g.z), h3 = __float2half_rn(g.w);
    uint2 hp; hp.x = (uint32_t)*(uint16_t*)&h0 | ((uint32_t)*(uint16_t*)&h1 << 16);
    hp.y = (uint32_t)*(uint16_t*)&h2 | ((uint32_t)*(uint16_t*)&h3 << 16);
    uint2 lp = packh4(g.x - __half2float(h0), g.y - __half2float(h1),
                      g.z - __half2float(h2), g.w - __half2float(h3));
    __half* base = g_att2 + (size_t)bt * 2 * VD_;
    *(uint2*)(base + k)       = hp;
    *(uint2*)(base + VD_ + k) = lp;
}

// ---------------- launch ----------------------------------------------------
extern "C" void kernel_launch(void* const* d_in, const int* in_sizes, int n_in,
                              void* d_out, int out_size)
{
    const float* x       = (const float*)d_in[0];
    const float* W_qkv   = (const float*)d_in[1];
    const float* W_z     = (const float*)d_in[2];
    const float* W_b     = (const float*)d_in[3];
    const float* W_a     = (const float*)d_in[4];
    const float* conv_w  = (const float*)d_in[5];
    const float* dt_bias = (const float*)d_in[6];
    const float* A_log   = (const float*)d_in[7];
    const float* norm_w  = (const float*)d_in[8];
    const float* W_out   = (const float*)d_in[9];

    float* out      = (float*)d_out;
    float* y        = out;
    float* s_final  = y + (size_t)BT_ * HID_;
    float* conv_buf = s_final + (size_t)B_ * NK_ * DK_ * SV_;

    void* p;
    cudaGetSymbolAddress(&p, g_qkv);   float* qkv  = (float*)p;
    cudaGetSymbolAddress(&p, g_zba);   float* zba  = (float*)p;
    cudaGetSymbolAddress(&p, g_x2);    __half* x2    = (__half*)p;
    cudaGetSymbolAddress(&p, g_wq2);   __half* wq2   = (__half*)p;
    cudaGetSymbolAddress(&p, g_wzba2); __half* wzba2 = (__half*)p;
    cudaGetSymbolAddress(&p, g_wo2);   __half* wo2   = (__half*)p;
    cudaGetSymbolAddress(&p, g_att2);  __half* att2  = (__half*)p;

    cudaFuncSetAttribute(gemm_fp16_mma, cudaFuncAttributeMaxDynamicSharedMemorySize, GEMM_SMEM);

    // 0. single prep launch: x split + weight splits + wba build
    prep_kernel<<<(int)(PN4 / 256), 256>>>(x, W_qkv, W_z, W_out, W_b, W_a);

    // 1. projections on tensor cores (K' = 2K); z+ba fused (N=4352)
    gemm_fp16_mma<<<dim3(QKV_/128, BT_/128), 128, GEMM_SMEM>>>(x2, wq2, qkv, BT_, QKV_, 2*HID_);
    gemm_fp16_mma<<<dim3(NZB_/128, BT_/128), 128, GEMM_SMEM>>>(x2, wzba2, zba, BT_, NZB_, 2*HID_);
    act_ba_kernel<<<(BT_*NV_ + 255)/256, 256>>>(dt_bias, A_log);

    // 2. conv + conv buffer output
    conv_kernel<<<(B_*(T_/4)*(QKV_/4) + 255)/256, 256>>>(conv_w);
    convbuf_kernel<<<(B_*QKV_*(KC_-1) + 255)/256, 256>>>(conv_buf);

    // 3. l2 normalize q,k heads in place
    l2norm_kernel<<<(BT_*2*NK_*32 + 255)/256, 256>>>();

    // 4. sequential scan (also emits S_final)
    scan_kernel<<<2*B_*NV_, 128>>>(s_final);

    // 5. RMSNorm + SiLU gate + fp16x2 split
    rmsgate_split_kernel<<<(BT_*NV_*32 + 255)/256, 256>>>(norm_w);

    // 6. output projection -> y
    gemm_fp16_mma<<<dim3(HID_/128, BT_/128), 128, GEMM_SMEM>>>(att2, wo2, y, BT_, HID_, 2*VD_);
}

// round 17
// speedup vs baseline: 1.1888x; 1.1771x over previous
#include <cuda_runtime.h>
#include <cuda_bf16.h>
#include <cuda_fp16.h>
#include <cstdint>
#include <math.h>

#define B_   2
#define T_   2048
#define HID_ 2048
#define NK_  16
#define DK_  128
#define NV_  32
#define DV_  128
#define KC_  4
#define P_   2
#define QD_  (NK_*DK_)        // 2048
#define VD_  (NV_*DV_)        // 4096
#define QKV_ (2*QD_+VD_)      // 8192
#define SV_  (P_*DV_)         // 256
#define BT_  (B_*T_)          // 4096
#define NZB_ (VD_ + 256)      // 4352 combined (z | ba-pad)

typedef unsigned long long u64;

// ---------------- scratch (device globals; no allocation allowed) ----------
__device__ __align__(16) float g_qkv [(size_t)BT_ * QKV_];   // raw qkv projection
__device__ __align__(16) float g_qkvc[(size_t)BT_ * QKV_];   // post-conv
__device__ __align__(16) float g_zba [(size_t)BT_ * NZB_];   // z | beta/dt pre-activation
__device__ __align__(16) float g_att [(size_t)BT_ * VD_];    // scan output
__device__ float g_beta [BT_ * NV_];
__device__ float g_decay[BT_ * NV_];

// input GEMM operands: plain fp16 (hi-only, K'=K)
__device__ __align__(16) __half g_x2   [(size_t)BT_  * HID_];
__device__ __align__(16) __half g_wq2  [(size_t)QKV_ * HID_];
__device__ __align__(16) __half g_wzba2[(size_t)NZB_ * HID_];   // W_z | W_ba(pad)
// output GEMM operands: fp16x2 split (K'=2K): A [hi|lo], B [hi|hi]
__device__ __align__(16) __half g_wo2  [(size_t)HID_ * 2 * VD_];
__device__ __align__(16) __half g_att2 [(size_t)BT_  * 2 * VD_];

// ================= PTX helpers ==============================================
__device__ __forceinline__ uint32_t smem_to_u32(const void* p) {
    uint32_t a;
    asm("{ .reg .u64 t; cvta.to.shared.u64 t, %1; cvt.u32.u64 %0, t; }" : "=r"(a) : "l"(p));
    return a;
}
__device__ __forceinline__ void cp_async16(uint32_t dst, const void* src) {
    asm volatile("cp.async.cg.shared.global [%0], [%1], 16;" :: "r"(dst), "l"(src) : "memory");
}
#define CP_COMMIT() asm volatile("cp.async.commit_group;" ::: "memory")
#define CP_WAIT1()  asm volatile("cp.async.wait_group 1;"  ::: "memory")

__device__ __forceinline__ void ldm_x4(uint32_t* r, uint32_t a) {
    asm volatile("ldmatrix.sync.aligned.m8n8.x4.shared.b16 {%0,%1,%2,%3}, [%4];"
        : "=r"(r[0]), "=r"(r[1]), "=r"(r[2]), "=r"(r[3]) : "r"(a));
}
__device__ __forceinline__ void mma16816(float* d, const uint32_t* a, uint32_t b0, uint32_t b1) {
    asm volatile("mma.sync.aligned.m16n8k16.row.col.f32.f16.f16.f32 "
        "{%0,%1,%2,%3}, {%4,%5,%6,%7}, {%8,%9}, {%0,%1,%2,%3};"
        : "+f"(d[0]), "+f"(d[1]), "+f"(d[2]), "+f"(d[3])
        : "r"(a[0]), "r"(a[1]), "r"(a[2]), "r"(a[3]), "r"(b0), "r"(b1));
}

// packed fp32x2 (Blackwell)
__device__ __forceinline__ u64 pack2(float lo, float hi) {
    u64 r; asm("mov.b64 %0, {%1,%2};" : "=l"(r) : "f"(lo), "f"(hi)); return r;
}
__device__ __forceinline__ void unpack2(u64 v, float& lo, float& hi) {
    asm("mov.b64 {%0,%1}, %2;" : "=f"(lo), "=f"(hi) : "l"(v));
}
__device__ __forceinline__ u64 fma2(u64 a, u64 b, u64 c) {
    u64 d; asm("fma.rn.f32x2 %0, %1, %2, %3;" : "=l"(d) : "l"(a), "l"(b), "l"(c)); return d;
}
__device__ __forceinline__ u64 mul2(u64 a, u64 b) {
    u64 d; asm("mul.rn.f32x2 %0, %1, %2;" : "=l"(d) : "l"(a), "l"(b)); return d;
}

// ================= fp16 NT GEMM via mma.sync ================================
// C[M,N] = A[M,K2] * B[N,K2]^T, fp32 accum.
// CTA tile 128(M) x 128(N), BK=64, 3 stages, 4 warps of 64x64, 128 threads,
// 2 CTAs/SM (measured-best config from R7/R10).
#define STAGES 3
#define A_BYTES 16384                    // 128 x 64 x 2
#define B_BYTES 16384                    // 128 x 64 x 2
#define STAGE_BYTES (A_BYTES + B_BYTES)  // 32KB
#define GEMM_SMEM (STAGES * STAGE_BYTES) // 96KB

__global__ __launch_bounds__(128, 2) void gemm_fp16_mma(
    const __half* __restrict__ A, const __half* __restrict__ Bw,
    float* __restrict__ C, int M, int N, int K2)
{
    extern __shared__ char smem[];
    const uint32_t s_base = smem_to_u32(smem);
    const int tid  = threadIdx.x;
    const int lane = tid & 31;
    const int wid  = tid >> 5;
    const int wm = wid & 1;        // 2 warp-rows (64 M each)
    const int wn = wid >> 1;       // 2 warp-cols (64 N each)
    const int bm = blockIdx.y * 128;
    const int bn = blockIdx.x * 128;

    const int lrow = tid >> 3;     // 0..15
    const int lchk = tid & 7;      // 16B chunk within 128B row
    const __half* Ag = A  + (size_t)(bm + lrow) * K2 + lchk * 8;
    const __half* Bg = Bw + (size_t)(bn + lrow) * K2 + lchk * 8;

    const int nchunks = K2 >> 6;

    float acc[4][8][4];
    #pragma unroll
    for (int i = 0; i < 4; i++)
        #pragma unroll
        for (int j = 0; j < 8; j++)
            #pragma unroll
            for (int k = 0; k < 4; k++) acc[i][j][k] = 0.f;

    const int jm = lane >> 3;
    const int rr = lane & 7;

    // prologue
    #pragma unroll
    for (int s = 0; s < STAGES - 1; s++) {
        const int k0 = s * 64;
        const uint32_t dA = s_base + s * STAGE_BYTES;
        const uint32_t dB = dA + A_BYTES;
        #pragma unroll
        for (int i = 0; i < 8; i++) {
            const int row = lrow + i * 16;
            const uint32_t off = (uint32_t)row * 128 + (uint32_t)((lchk ^ (row & 7)) * 16);
            cp_async16(dA + off, Ag + (size_t)i * 16 * K2 + k0);
            cp_async16(dB + off, Bg + (size_t)i * 16 * K2 + k0);
        }
        CP_COMMIT();
    }

    for (int c = 0; c < nchunks; c++) {
        CP_WAIT1();
        __syncthreads();

        const int nxt = c + STAGES - 1;
        if (nxt < nchunks) {
            const int s = nxt % STAGES;
            const int k0 = nxt * 64;
            const uint32_t dA = s_base + s * STAGE_BYTES;
            const uint32_t dB = dA + A_BYTES;
            #pragma unroll
            for (int i = 0; i < 8; i++) {
                const int row = lrow + i * 16;
                const uint32_t off = (uint32_t)row * 128 + (uint32_t)((lchk ^ (row & 7)) * 16);
                cp_async16(dA + off, Ag + (size_t)i * 16 * K2 + k0);
                cp_async16(dB + off, Bg + (size_t)i * 16 * K2 + k0);
            }
        }
        CP_COMMIT();

        const int s = c % STAGES;
        const uint32_t Ab = s_base + s * STAGE_BYTES;
        const uint32_t Bb = Ab + A_BYTES;
        #pragma unroll
        for (int ks = 0; ks < 4; ks++) {
            const int kc = ks * 2;
            uint32_t af[4][4];
            #pragma unroll
            for (int mi = 0; mi < 4; mi++) {
                const int r  = wm * 64 + mi * 16 + (jm & 1) * 8 + rr;
                const int cc = (kc + (jm >> 1)) ^ (r & 7);
                ldm_x4(af[mi], Ab + (uint32_t)(r * 128 + cc * 16));
            }
            uint32_t bf[4][4];
            #pragma unroll
            for (int nb = 0; nb < 4; nb++) {
                const int r  = wn * 64 + nb * 16 + (jm >> 1) * 8 + rr;
                const int cc = (kc + (jm & 1)) ^ (r & 7);
                ldm_x4(bf[nb], Bb + (uint32_t)(r * 128 + cc * 16));
            }
            #pragma unroll
            for (int mi = 0; mi < 4; mi++)
                #pragma unroll
                for (int ni = 0; ni < 8; ni++)
                    mma16816(acc[mi][ni], af[mi],
                             bf[ni >> 1][(ni & 1) * 2], bf[ni >> 1][(ni & 1) * 2 + 1]);
        }
        // no trailing __syncthreads — top-of-loop barrier orders stage reuse
    }

    // epilogue: fp32 direct store
    #pragma unroll
    for (int mi = 0; mi < 4; mi++) {
        const int row = bm + wm * 64 + mi * 16 + (lane >> 2);
        #pragma unroll
        for (int ni = 0; ni < 8; ni++) {
            const int col = bn + wn * 64 + ni * 8 + (lane & 3) * 2;
            *(float2*)(C + (size_t)row * N + col)       = make_float2(acc[mi][ni][0], acc[mi][ni][1]);
            *(float2*)(C + (size_t)(row + 8) * N + col) = make_float2(acc[mi][ni][2], acc[mi][ni][3]);
        }
    }
}

// ================= fp32 -> fp16 helpers =====================================
__device__ __forceinline__ uint2 packh4(float a, float b, float c, float d) {
    __half2 lo = __floats2half2_rn(a, b);
    __half2 hi = __floats2half2_rn(c, d);
    uint2 r; r.x = *(uint32_t*)&lo; r.y = *(uint32_t*)&hi; return r;
}
// plain fp32 -> fp16 convert (4 elements, contiguous layout)
__device__ __forceinline__ void cvt_one(const float* __restrict__ src,
                                        __half* __restrict__ dst, size_t i4)
{
    size_t idx = i4 * 4;
    float4 v = *(const float4*)(src + idx);
    __half h0 = __float2half_rn(v.x), h1 = __float2half_rn(v.y);
    __half h2 = __float2half_rn(v.z), h3 = __float2half_rn(v.w);
    uint2 hp; hp.x = (uint32_t)*(uint16_t*)&h0 | ((uint32_t)*(uint16_t*)&h1 << 16);
    hp.y = (uint32_t)*(uint16_t*)&h2 | ((uint32_t)*(uint16_t*)&h3 << 16);
    *(uint2*)(dst + idx) = hp;
}
// fp16x2 split, B-side [hi|hi], row-major K with 2K row stride
__device__ __forceinline__ void split_b(const float* __restrict__ src,
                                        __half* __restrict__ dst,
                                        int K, size_t i4)
{
    size_t idx = i4 * 4;
    int row = (int)(idx / K);
    int k   = (int)(idx % K);
    float4 v = *(const float4*)(src + idx);
    __half h0 = __float2half_rn(v.x), h1 = __float2half_rn(v.y);
    __half h2 = __float2half_rn(v.z), h3 = __float2half_rn(v.w);
    uint2 hp; hp.x = (uint32_t)*(uint16_t*)&h0 | ((uint32_t)*(uint16_t*)&h1 << 16);
    hp.y = (uint32_t)*(uint16_t*)&h2 | ((uint32_t)*(uint16_t*)&h3 << 16);
    __half* base = dst + (size_t)row * 2 * K;
    *(uint2*)(base + k)     = hp;
    *(uint2*)(base + K + k) = hp;
}

// ----- ONE prep launch: x/Wq/Wz/Wba fp16 convert + Wo fp16x2 split ---------
#define PN0 ((size_t)BT_  * HID_ / 4)          // x convert
#define PN1 (PN0 + (size_t)QKV_ * HID_ / 4)    // W_qkv convert
#define PN2 (PN1 + (size_t)VD_  * HID_ / 4)    // W_z convert
#define PN3 (PN2 + (size_t)HID_ * VD_  / 4)    // W_out split (B-side)
#define PN4 (PN3 + (size_t)256  * HID_ / 4)    // W_ba pad convert

__global__ void prep_kernel(const float* __restrict__ x,  const float* __restrict__ Wq,
                            const float* __restrict__ Wz, const float* __restrict__ Wo,
                            const float* __restrict__ Wb, const float* __restrict__ Wa)
{
    size_t i4 = (size_t)blockIdx.x * blockDim.x + threadIdx.x;
    if (i4 < PN0) { cvt_one(x, g_x2, i4); return; }
    if (i4 < PN1) { cvt_one(Wq, g_wq2, i4 - PN0); return; }
    if (i4 < PN2) { cvt_one(Wz, g_wzba2, i4 - PN1); return; }
    if (i4 < PN3) { split_b(Wo, g_wo2, VD_, i4 - PN2); return; }
    // W_ba padded rows into g_wzba2 at row offset VD_ (stride HID_)
    size_t r4 = i4 - PN3;
    size_t idx = r4 * 4;
    int row = (int)(idx / HID_);
    int k   = (int)(idx % HID_);
    float4 v = make_float4(0.f, 0.f, 0.f, 0.f);
    if (row < 32)      v = *(const float4*)(Wb + (size_t)row * HID_ + k);
    else if (row < 64) v = *(const float4*)(Wa + (size_t)(row - 32) * HID_ + k);
    __half h0 = __float2half_rn(v.x), h1 = __float2half_rn(v.y);
    __half h2 = __float2half_rn(v.z), h3 = __float2half_rn(v.w);
    uint2 hp; hp.x = (uint32_t)*(uint16_t*)&h0 | ((uint32_t)*(uint16_t*)&h1 << 16);
    hp.y = (uint32_t)*(uint16_t*)&h2 | ((uint32_t)*(uint16_t*)&h3 << 16);
    *(uint2*)(g_wzba2 + ((size_t)VD_ + row) * HID_ + k) = hp;
}

// beta/decay activations from combined z|ba buffer (cols VD_.., stride NZB_)
__global__ void act_ba_kernel(const float* __restrict__ dt_bias, const float* __restrict__ A_log)
{
    int idx = blockIdx.x * blockDim.x + threadIdx.x;
    if (idx >= BT_ * NV_) return;
    int row = idx / NV_, nv = idx % NV_;
    float sb = g_zba[(size_t)row * NZB_ + VD_ + nv];
    float sa = g_zba[(size_t)row * NZB_ + VD_ + 32 + nv];
    g_beta[idx] = 1.f / (1.f + expf(-sb));
    float aa = sa + dt_bias[nv];
    float sp = (aa > 20.f) ? aa : log1pf(expf(aa));
    g_decay[idx] = expf(-sp * expf(A_log[nv]));
}

// ---------- causal depthwise conv: 4 channels x 4 timesteps per thread -----
__global__ void conv_kernel(const float* __restrict__ cw)
{
    const int NC4 = QKV_ / 4;   // 2048
    const int NT4 = T_ / 4;     // 512
    int idx = blockIdx.x * blockDim.x + threadIdx.x;
    if (idx >= B_ * NT4 * NC4) return;
    const int c4 = idx % NC4;
    const int tmp = idx / NC4;
    const int t4 = tmp % NT4;
    const int b  = tmp / NT4;
    const int t0 = t4 * 4;
    const int c0 = c4 * 4;

    float4 w[4];
    #pragma unroll
    for (int ch = 0; ch < 4; ch++) w[ch] = *(const float4*)(cw + (size_t)(c0 + ch) * 4);

    const float* base = g_qkv + ((size_t)b * T_ + t0) * QKV_ + c0;
    float4 xv[7];
    #pragma unroll
    for (int d = 0; d < 7; d++) {
        const int t = t0 - 3 + d;
        xv[d] = (t >= 0) ? *(const float4*)(base + (ptrdiff_t)(d - 3) * QKV_)
                         : make_float4(0.f, 0.f, 0.f, 0.f);
    }
    float* outb = g_qkvc + ((size_t)b * T_ + t0) * QKV_ + c0;
    #pragma unroll
    for (int s = 0; s < 4; s++) {
        float4 y;
        y.x = xv[s].x*w[0].x + xv[s+1].x*w[0].y + xv[s+2].x*w[0].z + xv[s+3].x*w[0].w;
        y.y = xv[s].y*w[1].x + xv[s+1].y*w[1].y + xv[s+2].y*w[1].z + xv[s+3].y*w[1].w;
        y.z = xv[s].z*w[2].x + xv[s+1].z*w[2].y + xv[s+2].z*w[2].z + xv[s+3].z*w[2].w;
        y.w = xv[s].w*w[3].x + xv[s+1].w*w[3].y + xv[s+2].w*w[3].z + xv[s+3].w*w[3].w;
        *(float4*)(outb + (size_t)s * QKV_) = y;
    }
}

// ---------------- new_conv_buf: raw qkv rows T-3..T-1, transposed ----------
__global__ void convbuf_kernel(float* __restrict__ buf)
{
    int idx = blockIdx.x * blockDim.x + threadIdx.x;
    if (idx >= B_ * QKV_ * (KC_-1)) return;
    const int j = idx % (KC_-1);
    const int c = (idx / (KC_-1)) % QKV_;
    const int b = idx / ((KC_-1) * QKV_);
    buf[idx] = g_qkv[((size_t)(b * T_ + (T_ - (KC_-1) + j))) * QKV_ + c];
}

// ---------------- l2 normalize q and k heads (in place) --------------------
__global__ void l2norm_kernel()
{
    const int w = (blockIdx.x * blockDim.x + threadIdx.x) >> 5;
    const int lane = threadIdx.x & 31;
    if (w >= BT_ * 2 * NK_) return;
    const int h = w % (2 * NK_);
    const size_t bt = (size_t)(w / (2 * NK_));
    float* base = g_qkvc + bt * QKV_ + (size_t)h * DK_;
    float4 v = *(float4*)(base + lane * 4);
    float s = v.x*v.x + v.y*v.y + v.z*v.z + v.w*v.w;
    #pragma unroll
    for (int o = 16; o; o >>= 1) s += __shfl_xor_sync(0xffffffffu, s, o);
    const float inv = 1.f / fmaxf(sqrtf(s), 1e-12f);
    v.x *= inv; v.y *= inv; v.z *= inv; v.w *= inv;
    *(float4*)(base + lane * 4) = v;
}

// ---- sequential gated delta-rule scan (deferred decay, f32x2, col-split x2)
// 128 CTAs: CTA = (b, nv, half). 128 threads: pair (jloc, h) — thread owns
// rows h*64..h*64+63 (as 32 f32x2 pairs) of column j = half*64 + jloc.
// R14 form exactly (u64 smem loads; LDS.128 variant regressed in R15).
__global__ __launch_bounds__(128, 1) void scan_kernel(float* __restrict__ s_final)
{
    const int bx   = blockIdx.x;
    const int half = bx & 1;
    const int bnv  = bx >> 1;
    const int b  = bnv / NV_;
    const int nv = bnv % NV_;
    const int nk = nv >> 1;
    const int p  = nv & 1;
    const int tid  = threadIdx.x;
    const int jloc = tid >> 1;
    const int h    = tid & 1;
    const int j    = half * 64 + jloc;
    const int hoff = h * 64;

    u64 Sa[32];
    #pragma unroll
    for (int i = 0; i < 32; i++) Sa[i] = 0ull;
    float D = 1.f;

    __shared__ __align__(16) float qs[2][128];
    __shared__ __align__(16) float ks[2][128];

    const float* base = g_qkvc + (size_t)b * T_ * QKV_;
    const int row0 = b * T_;

    // prologue: t = 0
    qs[0][tid] = base[nk * DK_ + tid];
    ks[0][tid] = base[QD_ + nk * DK_ + tid];
    float v  = base[2 * QD_ + nv * DV_ + j];
    float be = g_beta [row0 * NV_ + nv];
    float de = g_decay[row0 * NV_ + nv];
    __syncthreads();

    for (int t = 0; t < T_; t++) {
        // prefetch t+1 into registers (LDG hidden under compute)
        float qn = 0.f, kn = 0.f, vn = 0.f, ben = 0.f, den = 0.f;
        if (t + 1 < T_) {
            const float* rown = base + (size_t)(t + 1) * QKV_;
            qn  = rown[nk * DK_ + tid];
            kn  = rown[QD_ + nk * DK_ + tid];
            vn  = rown[2 * QD_ + nv * DV_ + j];
            ben = g_beta [(row0 + t + 1) * NV_ + nv];
            den = g_decay[(row0 + t + 1) * NV_ + nv];
        }
        const int buf = t & 1;
        const u64* k2 = (const u64*)(ks[buf] + hoff);
        const u64* q2 = (const u64*)(qs[buf] + hoff);

        u64 kk[32];
        #pragma unroll
        for (int i = 0; i < 32; i++) kk[i] = k2[i];

        // partial sk = k[h-rows] . Sa  (packed); true sk = D * total
        u64 a0 = 0ull, a1 = 0ull, a2 = 0ull, a3 = 0ull;
        #pragma unroll
        for (int i = 0; i < 32; i += 4) {
            a0 = fma2(kk[i+0], Sa[i+0], a0);
            a1 = fma2(kk[i+1], Sa[i+1], a1);
            a2 = fma2(kk[i+2], Sa[i+2], a2);
            a3 = fma2(kk[i+3], Sa[i+3], a3);
        }
        float x0, x1, x2, x3, x4, x5, x6, x7;
        unpack2(a0, x0, x1); unpack2(a1, x2, x3);
        unpack2(a2, x4, x5); unpack2(a3, x6, x7);
        float skp = ((x0 + x1) + (x2 + x3)) + ((x4 + x5) + (x6 + x7));
        skp += __shfl_xor_sync(0xffffffffu, skp, 1);
        const float sk = D * skp;
        const float dv = be * (v - sk);
        const float Dn = D * de;

        // S_true_new = Dn * Sa_new
        u64 o0 = 0ull, o1 = 0ull, o2 = 0ull, o3 = 0ull;
        float o_scale;
        if (Dn >= 1e-12f) {
            // normal: Sa += (dv/Dn) * k   (1 fma2/pair)
            const float c = __fdividef(dv, Dn);
            const u64 c2 = pack2(c, c);
            #pragma unroll
            for (int i = 0; i < 32; i += 4) {
                Sa[i+0] = fma2(c2, kk[i+0], Sa[i+0]);  o0 = fma2(q2[i+0], Sa[i+0], o0);
                Sa[i+1] = fma2(c2, kk[i+1], Sa[i+1]);  o1 = fma2(q2[i+1], Sa[i+1], o1);
                Sa[i+2] = fma2(c2, kk[i+2], Sa[i+2]);  o2 = fma2(q2[i+2], Sa[i+2], o2);
                Sa[i+3] = fma2(c2, kk[i+3], Sa[i+3]);  o3 = fma2(q2[i+3], Sa[i+3], o3);
            }
            D = Dn;
            o_scale = Dn;
        } else {
            // renormalize: Sa = Dn*Sa + dv*k ; D = 1
            const u64 s2  = pack2(Dn, Dn);
            const u64 dv2 = pack2(dv, dv);
            #pragma unroll
            for (int i = 0; i < 32; i += 4) {
                Sa[i+0] = fma2(s2, Sa[i+0], mul2(dv2, kk[i+0]));  o0 = fma2(q2[i+0], Sa[i+0], o0);
                Sa[i+1] = fma2(s2, Sa[i+1], mul2(dv2, kk[i+1]));  o1 = fma2(q2[i+1], Sa[i+1], o1);
                Sa[i+2] = fma2(s2, Sa[i+2], mul2(dv2, kk[i+2]));  o2 = fma2(q2[i+2], Sa[i+2], o2);
                Sa[i+3] = fma2(s2, Sa[i+3], mul2(dv2, kk[i+3]));  o3 = fma2(q2[i+3], Sa[i+3], o3);
            }
            D = 1.f;
            o_scale = 1.f;
        }
        unpack2(o0, x0, x1); unpack2(o1, x2, x3);
        unpack2(o2, x4, x5); unpack2(o3, x6, x7);
        float op = ((x0 + x1) + (x2 + x3)) + ((x4 + x5) + (x6 + x7));
        op += __shfl_xor_sync(0xffffffffu, op, 1);
        if (h == 0)
            g_att[((size_t)(row0 + t) * NV_ + nv) * DV_ + j] = o_scale * op;

        // stage t+1 into alternate buffer
        if (t + 1 < T_) {
            qs[buf ^ 1][tid] = qn;
            ks[buf ^ 1][tid] = kn;
        }
        v = vn; be = ben; de = den;
        __syncthreads();
    }

    // S_final [B, NK, DK, P*DV] = D * Sa
    #pragma unroll
    for (int i = 0; i < 32; i++) {
        float lo, hi;
        unpack2(Sa[i], lo, hi);
        const size_t rbase = (((size_t)b * NK_ + nk) * DK_ + (hoff + 2 * i));
        s_final[(rbase * P_ + p) * DV_ + j]         = D * lo;
        s_final[((rbase + 1) * P_ + p) * DV_ + j]   = D * hi;
    }
}

// ------- RMSNorm + SiLU gate, fused with fp16x2 A-side split ---------------
// z read from combined z|ba buffer (cols 0..VD_-1, row stride NZB_).
__global__ void rmsgate_split_kernel(const float* __restrict__ norm_w)
{
    const int w = (blockIdx.x * blockDim.x + threadIdx.x) >> 5;
    const int lane = threadIdx.x & 31;
    if (w >= BT_ * NV_) return;
    const size_t off = (size_t)w * DV_ + lane * 4;
    float4 o = *(float4*)(g_att + off);
    float ss = o.x*o.x + o.y*o.y + o.z*o.z + o.w*o.w;
    #pragma unroll
    for (int k = 16; k; k >>= 1) ss += __shfl_xor_sync(0xffffffffu, ss, k);
    const float r = rsqrtf(ss * (1.f / DV_) + 1e-6f);
    const int bt = w / NV_;
    const int k  = (w % NV_) * DV_ + lane * 4;
    float4 z  = *(float4*)(g_zba + (size_t)bt * NZB_ + k);
    float4 nw = *(const float4*)(norm_w + lane * 4);
    float4 g;
    g.x = o.x * r * nw.x * (z.x / (1.f + expf(-z.x)));
    g.y = o.y * r * nw.y * (z.y / (1.f + expf(-z.y)));
    g.z = o.z * r * nw.z * (z.z / (1.f + expf(-z.z)));
    g.w = o.w * r * nw.w * (z.w / (1.f + expf(-z.w)));

    __half h0 = __float2half_rn(g.x), h1 = __float2half_rn(g.y);
    __half h2 = __float2half_rn(g.z), h3 = __float2half_rn(g.w);
    uint2 hp; hp.x = (uint32_t)*(uint16_t*)&h0 | ((uint32_t)*(uint16_t*)&h1 << 16);
    hp.y = (uint32_t)*(uint16_t*)&h2 | ((uint32_t)*(uint16_t*)&h3 << 16);
    uint2 lp = packh4(g.x - __half2float(h0), g.y - __half2float(h1),
                      g.z - __half2float(h2), g.w - __half2float(h3));
    __half* base = g_att2 + (size_t)bt * 2 * VD_;
    *(uint2*)(base + k)       = hp;
    *(uint2*)(base + VD_ + k) = lp;
}

// ---------------- launch ----------------------------------------------------
extern "C" void kernel_launch(void* const* d_in, const int* in_sizes, int n_in,
                              void* d_out, int out_size)
{
    const float* x       = (const float*)d_in[0];
    const float* W_qkv   = (const float*)d_in[1];
    const float* W_z     = (const float*)d_in[2];
    const float* W_b     = (const float*)d_in[3];
    const float* W_a     = (const float*)d_in[4];
    const float* conv_w  = (const float*)d_in[5];
    const float* dt_bias = (const float*)d_in[6];
    const float* A_log   = (const float*)d_in[7];
    const float* norm_w  = (const float*)d_in[8];
    const float* W_out   = (const float*)d_in[9];

    float* out      = (float*)d_out;
    float* y        = out;
    float* s_final  = y + (size_t)BT_ * HID_;
    float* conv_buf = s_final + (size_t)B_ * NK_ * DK_ * SV_;

    void* p;
    cudaGetSymbolAddress(&p, g_qkv);   float* qkv  = (float*)p;
    cudaGetSymbolAddress(&p, g_zba);   float* zba  = (float*)p;
    cudaGetSymbolAddress(&p, g_x2);    __half* x2    = (__half*)p;
    cudaGetSymbolAddress(&p, g_wq2);   __half* wq2   = (__half*)p;
    cudaGetSymbolAddress(&p, g_wzba2); __half* wzba2 = (__half*)p;
    cudaGetSymbolAddress(&p, g_wo2);   __half* wo2   = (__half*)p;
    cudaGetSymbolAddress(&p, g_att2);  __half* att2  = (__half*)p;

    cudaFuncSetAttribute(gemm_fp16_mma, cudaFuncAttributeMaxDynamicSharedMemorySize, GEMM_SMEM);

    // 0. single prep launch: fp16 converts + W_out split
    prep_kernel<<<(int)(PN4 / 256), 256>>>(x, W_qkv, W_z, W_out, W_b, W_a);

    // 1. input projections hi-only fp16 (K' = K); z+ba fused (N=4352)
    gemm_fp16_mma<<<dim3(QKV_/128, BT_/128), 128, GEMM_SMEM>>>(x2, wq2, qkv, BT_, QKV_, HID_);
    gemm_fp16_mma<<<dim3(NZB_/128, BT_/128), 128, GEMM_SMEM>>>(x2, wzba2, zba, BT_, NZB_, HID_);
    act_ba_kernel<<<(BT_*NV_ + 255)/256, 256>>>(dt_bias, A_log);

    // 2. conv + conv buffer output
    conv_kernel<<<(B_*(T_/4)*(QKV_/4) + 255)/256, 256>>>(conv_w);
    convbuf_kernel<<<(B_*QKV_*(KC_-1) + 255)/256, 256>>>(conv_buf);

    // 3. l2 normalize q,k heads in place
    l2norm_kernel<<<(BT_*2*NK_*32 + 255)/256, 256>>>();

    // 4. sequential scan (also emits S_final)
    scan_kernel<<<2*B_*NV_, 128>>>(s_final);

    // 5. RMSNorm + SiLU gate + fp16x2 split
    rmsgate_split_kernel<<<(BT_*NV_*32 + 255)/256, 256>>>(norm_w);

    // 6. output projection -> y (fp16x2, K' = 2*VD)
    gemm_fp16_mma<<<dim3(HID_/128, BT_/128), 128, GEMM_SMEM>>>(att2, wo2, y, BT_, HID_, 2*VD_);
}